// round 11
// baseline (speedup 1.0000x reference)
#include <cuda_runtime.h>
#include <math.h>

#define BN 8
#define XN 128
#define YN 128
#define YHN 65
#define WCH 24
#define DL 4
#define TSTEPS 8
#define NPAIR 12
#define PTS (XN*YHN)       // 8320
#define QN (BN*WCH)        // 192

// Conventions: spatial y stored BIT-REVERSED (7-bit) in d_h.
// kx stored bit-reversed ("kxs") in d_Hf/d_Yf; k_spec maps weights via brev7.

__device__ float  d_h [BN*WCH*XN*YN];                  // [b][c][x][yb]
__device__ __align__(16) float4 d_Hy[BN*YHN*NPAIR*XN]; // [b][ky][pair][x]
__device__ __align__(16) float2 d_Hf[PTS*QN];          // [(kxs*65+ky)][q]
__device__ __align__(16) float4 d_Yf[BN*YHN*NPAIR*XN]; // [b][ky][pair][kxs]
__device__ __align__(16) float4 d_Gy[BN*NPAIR*XN*YHN]; // [b][pair][x][ky]

__device__ __forceinline__ float2 cmul(float2 a, float2 b){
    return make_float2(fmaf(a.x,b.x,-a.y*b.y), fmaf(a.x,b.y, a.y*b.x));
}
__device__ __forceinline__ float2 cadd(float2 a, float2 b){ return make_float2(a.x+b.x, a.y+b.y); }
__device__ __forceinline__ float2 csub(float2 a, float2 b){ return make_float2(a.x-b.x, a.y-b.y); }

struct Tw { float2 w1, w1b, w2, w4, w8, w16, w32; };

template<bool INV>
__device__ __forceinline__ float2 tsel(float2 w){ return INV ? make_float2(w.x, -w.y) : w; }

__device__ __forceinline__ Tw make_tw(int l){
    Tw t; float s, c;
    const float P = -6.2831853071795864769f;
    sincosf(P*(float)l/128.f, &s, &c);       t.w1  = make_float2(c, s);
    t.w1b = make_float2(t.w1.y, -t.w1.x);
    t.w2  = cmul(t.w1, t.w1);
    sincosf(P*(float)(l&15)/32.f, &s, &c);   t.w4  = make_float2(c, s);
    sincosf(P*(float)(l&7)/16.f,  &s, &c);   t.w8  = make_float2(c, s);
    sincosf(P*(float)(l&3)/8.f,   &s, &c);   t.w16 = make_float2(c, s);
    t.w32 = (l&1) ? make_float2(0.f, -1.f) : make_float2(1.f, 0.f);
    return t;
}

__device__ __forceinline__ void dif_x4(float2 v[4], int m, float2 w, int l){
    #pragma unroll
    for (int r = 0; r < 4; r++){
        float2 p;
        p.x = __shfl_xor_sync(0xffffffffu, v[r].x, m);
        p.y = __shfl_xor_sync(0xffffffffu, v[r].y, m);
        v[r] = (l & m) ? cmul(csub(p, v[r]), w) : cadd(v[r], p);
    }
}
__device__ __forceinline__ void dit_x4(float2 v[4], int m, float2 w, int l){
    #pragma unroll
    for (int r = 0; r < 4; r++){
        float2 b = (l & m) ? cmul(v[r], w) : v[r];
        float2 p;
        p.x = __shfl_xor_sync(0xffffffffu, b.x, m);
        p.y = __shfl_xor_sync(0xffffffffu, b.y, m);
        v[r] = (l & m) ? csub(p, b) : cadd(b, p);
    }
}

template<bool INV>
__device__ __forceinline__ void fft_dif(float2 v[4], const Tw& t, int l){
    const float2 one = make_float2(1.f, 0.f);
    float2 w1 = tsel<INV>(t.w1), w1b = tsel<INV>(t.w1b), w2 = tsel<INV>(t.w2);
    float2 tm;
    tm = csub(v[0], v[2]); v[0] = cadd(v[0], v[2]); v[2] = cmul(tm, w1);
    tm = csub(v[1], v[3]); v[1] = cadd(v[1], v[3]); v[3] = cmul(tm, w1b);
    tm = csub(v[0], v[1]); v[0] = cadd(v[0], v[1]); v[1] = cmul(tm, w2);
    tm = csub(v[2], v[3]); v[2] = cadd(v[2], v[3]); v[3] = cmul(tm, w2);
    dif_x4(v, 16, tsel<INV>(t.w4),  l);
    dif_x4(v,  8, tsel<INV>(t.w8),  l);
    dif_x4(v,  4, tsel<INV>(t.w16), l);
    dif_x4(v,  2, tsel<INV>(t.w32), l);
    dif_x4(v,  1, one, l);
}

template<bool INV>
__device__ __forceinline__ void fft_dit(float2 v[4], const Tw& t, int l){
    const float2 one = make_float2(1.f, 0.f);
    dit_x4(v,  1, one, l);
    dit_x4(v,  2, tsel<INV>(t.w32), l);
    dit_x4(v,  4, tsel<INV>(t.w16), l);
    dit_x4(v,  8, tsel<INV>(t.w8),  l);
    dit_x4(v, 16, tsel<INV>(t.w4),  l);
    float2 w1 = tsel<INV>(t.w1), w1b = tsel<INV>(t.w1b), w2 = tsel<INV>(t.w2);
    float2 b;
    b = cmul(v[1], w2);  v[1] = csub(v[0], b); v[0] = cadd(v[0], b);
    b = cmul(v[3], w2);  v[3] = csub(v[2], b); v[2] = cadd(v[2], b);
    b = cmul(v[2], w1);  v[2] = csub(v[0], b); v[0] = cadd(v[0], b);
    b = cmul(v[3], w1b); v[3] = csub(v[1], b); v[1] = cadd(v[1], b);
}

__device__ __forceinline__ int brev7(int i){ return (int)(__brev((unsigned)i) >> 25); }

// Forward packed Y-FFT of one channel pair from smem row hn[yb*25 + c], write d_Hy.
__device__ __forceinline__ void ffty_pair(const float* hn, int b, int x, int pr,
                                          const Tw& tw, int l){
    float2 v[4];
    #pragma unroll
    for (int r = 0; r < 4; r++){
        int p = r*32 + l;
        v[r] = make_float2(hn[p*25 + 2*pr], hn[p*25 + 2*pr + 1]);
    }
    fft_dit<false>(v, tw, l);                     // natural ky = r*32+l
    int srcl = (32 - l) & 31;
    float2 s3, s2;
    s3.x = __shfl_sync(0xffffffffu, v[3].x, srcl);
    s3.y = __shfl_sync(0xffffffffu, v[3].y, srcl);
    s2.x = __shfl_sync(0xffffffffu, v[2].x, srcl);
    s2.y = __shfl_sync(0xffffffffu, v[2].y, srcl);
    float2 zm0 = (l == 0) ? v[0] : s3;            // partner of ky=l
    float2 zm1 = (l == 0) ? s3   : s2;            // partner of ky=32+l
    float4* hy = d_Hy + ((size_t)b*YHN*NPAIR + pr)*XN + x;
    float2 zk;
    zk = v[0];                                    // ky = l
    hy[(size_t)l*NPAIR*XN] = make_float4(
        0.5f*(zk.x+zm0.x), 0.5f*(zk.y-zm0.y),
        0.5f*(zk.y+zm0.y), 0.5f*(zm0.x-zk.x));
    zk = v[1];                                    // ky = 32+l
    hy[(size_t)(32+l)*NPAIR*XN] = make_float4(
        0.5f*(zk.x+zm1.x), 0.5f*(zk.y-zm1.y),
        0.5f*(zk.y+zm1.y), 0.5f*(zm1.x-zk.x));
    if (l == 0){                                  // ky = 64
        zk = v[2];
        hy[(size_t)64*NPAIR*XN] = make_float4(zk.x, 0.f, zk.y, 0.f);
    }
}

// ---------------- k_first: h0 = x@in_w+in_b (bitrev-y) + forward Y-FFT ------
__global__ __launch_bounds__(384) void k_first(const float* __restrict__ xin,
                                               const float* __restrict__ inw,
                                               const float* __restrict__ inb){
    __shared__ float2 xv[XN];
    __shared__ float  hn[YN*25];
    int tid = threadIdx.x, wl = tid >> 5, l = tid & 31;
    int bx = blockIdx.x, b = bx >> 7, x = bx & 127;
    if (tid < XN)
        xv[tid] = *(const float2*)(xin + (((size_t)(b*XN + x))*YN + tid)*2);
    __syncthreads();
    for (int idx = tid; idx < WCH*YN; idx += 384){
        int c = idx >> 7, yb = idx & 127;
        float2 v = xv[brev7(yb)];
        float val = inb[c] + v.x*inw[c] + v.y*inw[WCH + c];
        hn[yb*25 + c] = val;
        d_h[((size_t)(b*WCH + c)*XN + x)*YN + yb] = val;
    }
    __syncthreads();
    Tw tw = make_tw(l);
    ffty_pair(hn, b, x, wl, tw, l);
}

// ---- X-FFT (complex, both channels), warp per (b,ky,pair) -----------------
__global__ __launch_bounds__(256) void k_fftx(){
    int tid = threadIdx.x, wl = tid >> 5, l = tid & 31;
    int wid = blockIdx.x*8 + wl;
    int pr = wid % NPAIR;
    int ky = (wid / NPAIR) % YHN;
    int b  = wid / (NPAIR*YHN);
    Tw tw = make_tw(l);
    const float4* src = d_Hy + (((size_t)b*YHN + ky)*NPAIR + pr)*XN;
    float2 v[4], u[4];
    #pragma unroll
    for (int r = 0; r < 4; r++){
        float4 f = src[r*32 + l];
        v[r] = make_float2(f.x, f.y);
        u[r] = make_float2(f.z, f.w);
    }
    fft_dif<false>(v, tw, l);
    fft_dif<false>(u, tw, l);
    int q0 = b*WCH + 2*pr;
    #pragma unroll
    for (int r = 0; r < 4; r++){
        int kxs = r*32 + l;
        *(float4*)(d_Hf + ((size_t)kxs*YHN + ky)*QN + q0)
            = make_float4(v[r].x, v[r].y, u[r].x, u[r].y);
    }
}

// ---------------- per-point complex channel mix ----------------------------
// 780 blocks: blockIdx = pg*3 + g (3 output groups share the H tile in L2).
// Warp = (pair-of-outputs pw, batch-half): 8 float2 accumulators, direct write.
__device__ __forceinline__ int hsw(int q, int t){ return q*32 + ((t + q) & 31); }

__global__ __launch_bounds__(256) void k_spec(const float2* __restrict__ specw, int d){
    __shared__ float2 Hs[QN*32];
    int tid = threadIdx.x;
    int pg = blockIdx.x / 3, g = blockIdx.x - pg*3;
    int p0 = pg * 32;
    for (int idx = tid; idx < 32*QN; idx += 256){
        int t = idx / QN, q = idx - t*QN;
        Hs[hsw(q, t)] = d_Hf[(size_t)(p0 + t)*QN + q];
    }
    __syncthreads();
    int w = tid >> 5, lane = tid & 31;
    int pw = w >> 1, half = w & 1;
    int pr = g*4 + pw;                     // global pair 0..11
    int o0 = 2*pr;
    int p   = p0 + lane;
    int kxs = p / 65;
    int ky  = p - kxs*65;
    int pb  = brev7(kxs)*65 + ky;          // true weight column
    const float2* wpa = specw + ((size_t)(d*576 + o0    ))*PTS + pb;
    const float2* wpb = specw + ((size_t)(d*576 + o0 + 1))*PTS + pb;
    float2 A[4], B[4];
    #pragma unroll
    for (int bb = 0; bb < 4; bb++){
        A[bb] = make_float2(0.f, 0.f);
        B[bb] = make_float2(0.f, 0.f);
    }
    int qb = half*4*WCH;                   // batch base in Hs q-index
    // software pipeline depth 2 (step per i = WCH*PTS complex elements)
    float2 a0 = wpa[0];
    float2 b0 = wpb[0];
    float2 a1 = wpa[(size_t)WCH*PTS];
    float2 b1 = wpb[(size_t)WCH*PTS];
    for (int i = 0; i < WCH; i++){
        int ip = (i + 2 < WCH) ? i + 2 : WCH - 1;
        float2 a2 = wpa[(size_t)ip*WCH*PTS];
        float2 b2 = wpb[(size_t)ip*WCH*PTS];
        float2 hv[4];
        #pragma unroll
        for (int bb = 0; bb < 4; bb++) hv[bb] = Hs[hsw(qb + bb*WCH + i, lane)];
        #pragma unroll
        for (int bb = 0; bb < 4; bb++){
            A[bb].x = fmaf( hv[bb].x, a0.x, A[bb].x);
            A[bb].x = fmaf(-hv[bb].y, a0.y, A[bb].x);
            A[bb].y = fmaf( hv[bb].x, a0.y, A[bb].y);
            A[bb].y = fmaf( hv[bb].y, a0.x, A[bb].y);
            B[bb].x = fmaf( hv[bb].x, b0.x, B[bb].x);
            B[bb].x = fmaf(-hv[bb].y, b0.y, B[bb].x);
            B[bb].y = fmaf( hv[bb].x, b0.y, B[bb].y);
            B[bb].y = fmaf( hv[bb].y, b0.x, B[bb].y);
        }
        a0 = a1; b0 = b1; a1 = a2; b1 = b2;
    }
    // direct transposed write: d_Yf[b][ky][pair][kxs], channel pair packed
    #pragma unroll
    for (int bb = 0; bb < 4; bb++){
        int b = half*4 + bb;
        d_Yf[(((size_t)b*YHN + ky)*NPAIR + pr)*XN + kxs]
            = make_float4(A[bb].x, A[bb].y, B[bb].x, B[bb].y);
    }
}

// ---- inverse X-FFT, warp per (b,ky,pair): coalesced read, scattered write --
__global__ __launch_bounds__(256) void k_ifftx(){
    int tid = threadIdx.x, wl = tid >> 5, l = tid & 31;
    int wid = blockIdx.x*8 + wl;
    int pr = wid % NPAIR;
    int ky = (wid / NPAIR) % YHN;
    int b  = wid / (NPAIR*YHN);
    Tw tw = make_tw(l);
    const float4* src = d_Yf + (((size_t)b*YHN + ky)*NPAIR + pr)*XN;
    float2 v[4], u[4];
    #pragma unroll
    for (int r = 0; r < 4; r++){
        float4 f = src[r*32 + l];                 // contiguous 2KB per warp
        v[r] = make_float2(f.x, f.y);
        u[r] = make_float2(f.z, f.w);
    }
    fft_dit<true>(v, tw, l);
    fft_dit<true>(u, tw, l);
    float4* dst = d_Gy + (((size_t)b*NPAIR + pr)*XN)*YHN + ky;  // + x*YHN
    #pragma unroll
    for (int r = 0; r < 4; r++){
        int x = r*32 + l;
        dst[(size_t)x*YHN] = make_float4(v[r].x, v[r].y, u[r].x, u[r].y);
    }
}

// ---- k_tail: inverse Y-rFFT + conv + h update + out proj + next Y-FFT -----
__global__ __launch_bounds__(384) void k_tail(const float* __restrict__ convw,
                                              const float* __restrict__ convb,
                                              const float* __restrict__ outw,
                                              const float* __restrict__ outb,
                                              float* __restrict__ out,
                                              int d, int t, int last, int do_fft){
    __shared__ float hrow [WCH*YN];   // [c][yb]
    __shared__ float x1row[YN*25];    // [yb][c]
    __shared__ float hn   [YN*25];    // [yb][c]
    __shared__ float cw[WCH*WCH];
    __shared__ float cb[WCH];
    __shared__ float ow[WCH];
    __shared__ float ob;
    int tid = threadIdx.x, wl = tid >> 5, l = tid & 31;
    int bx = blockIdx.x, b = bx >> 7, x = bx & 127;
    Tw tw = make_tw(l);
    float* hpb = d_h + (size_t)b*WCH*XN*YN + (size_t)x*YN;
    for (int idx = tid; idx < WCH*YN; idx += 384){
        int c = idx >> 7, y = idx & 127;
        hrow[idx] = hpb[(size_t)c*XN*YN + y];
    }
    for (int idx = tid; idx < WCH*WCH; idx += 384) cw[idx] = convw[d*WCH*WCH + idx];
    if (tid < WCH){ cb[tid] = convb[d*WCH + tid]; ow[tid] = outw[tid]; }
    if (tid == 0) ob = outb[0];
    // inverse Y (packed pair): warp wl = pair; coalesced d_Gy rows
    {
        int pr = wl;
        const float4* gy = d_Gy + (((size_t)b*NPAIR + pr)*XN + x)*YHN;
        float2 z[4];
        {   // k = l (DC imag discarded at l==0)
            float4 f = gy[l];
            float2 g0 = make_float2(f.x, f.y), g1 = make_float2(f.z, f.w);
            if (l == 0){ g0.y = 0.f; g1.y = 0.f; }
            z[0] = make_float2(g0.x - g1.y, g0.y + g1.x);
        }
        {   // k = 32+l
            float4 f = gy[32 + l];
            z[1] = make_float2(f.x - f.w, f.y + f.z);
        }
        {   // k = 64+l: l==0 direct (Nyquist); else mirror km=64-l
            int km = 64 - l;
            float4 f = gy[km];
            float2 g0 = make_float2(f.x, f.y), g1 = make_float2(f.z, f.w);
            if (l == 0){
                g0.y = 0.f; g1.y = 0.f;
                z[2] = make_float2(g0.x - g1.y, g0.y + g1.x);
            } else {
                z[2] = make_float2(g0.x + g1.y, g1.x - g0.y);
            }
        }
        {   // k = 96+l: mirror km = 32-l
            int km = 32 - l;
            float4 f = gy[km];
            z[3] = make_float2(f.x + f.w, f.z - f.y);
        }
        fft_dif<true>(z, tw, l);
        const float sc = 1.f/16384.f;
        #pragma unroll
        for (int r = 0; r < 4; r++){
            int p = r*32 + l;
            x1row[p*25 + 2*pr    ] = z[r].x * sc;
            x1row[p*25 + 2*pr + 1] = z[r].y * sc;
        }
    }
    __syncthreads();
    // conv + relu-combine: thread -> (y, o-group of 8)
    {
        int y = tid & 127, og = tid >> 7, o0 = og*8;
        float acc[8];
        #pragma unroll
        for (int j = 0; j < 8; j++) acc[j] = cb[o0 + j];
        #pragma unroll
        for (int i = 0; i < WCH; i++){
            float hv = hrow[i*YN + y];
            #pragma unroll
            for (int j = 0; j < 8; j++) acc[j] = fmaf(hv, cw[i*WCH + o0 + j], acc[j]);
        }
        #pragma unroll
        for (int j = 0; j < 8; j++){
            float v = x1row[y*25 + o0 + j];
            hn[y*25 + o0 + j] = fmaxf(v, 0.f) + acc[j];
        }
    }
    __syncthreads();
    for (int idx = tid; idx < WCH*YN; idx += 384){
        int c = idx >> 7, yy = idx & 127;
        hpb[(size_t)c*XN*YN + yy] = hn[yy*25 + c];
    }
    if (last){
        for (int yy = tid; yy < YN; yy += 384){
            float a = ob;
            #pragma unroll
            for (int c = 0; c < WCH; c++) a = fmaf(hn[yy*25 + c], ow[c], a);
            out[(((size_t)b*TSTEPS + t)*XN + x)*YN + brev7(yy)] = a;
        }
    }
    if (do_fft)
        ffty_pair(hn, b, x, wl, tw, l);
}

// ---------------------------------------------------------------------------
extern "C" void kernel_launch(void* const* d_in, const int* in_sizes, int n_in,
                              void* d_out, int out_size){
    (void)in_sizes; (void)n_in; (void)out_size;
    const float* x     = (const float*)d_in[0];
    const float* in_w  = (const float*)d_in[1];
    const float* in_b  = (const float*)d_in[2];
    const float2* specw= (const float2*)d_in[3];
    const float* convw = (const float*)d_in[4];
    const float* convb = (const float*)d_in[5];
    const float* outw  = (const float*)d_in[6];
    const float* outb  = (const float*)d_in[7];
    float* out = (float*)d_out;

    k_first<<<BN*XN, 384>>>(x, in_w, in_b);
    for (int t = 0; t < TSTEPS; t++){
        for (int d = 0; d < DL; d++){
            k_fftx <<<BN*YHN*NPAIR/8, 256>>>();
            k_spec <<<(PTS/32)*3    , 256>>>(specw, d);
            k_ifftx<<<BN*YHN*NPAIR/8, 256>>>();
            int last   = (d == DL-1);
            int do_fft = !(t == TSTEPS-1 && d == DL-1);
            k_tail <<<BN*XN         , 384>>>(convw, convb, outw, outb, out, d, t, last, do_fft);
        }
    }
}

// round 12
// speedup vs baseline: 1.3171x; 1.3171x over previous
#include <cuda_runtime.h>
#include <math.h>

#define BN 8
#define XN 128
#define YN 128
#define YHN 65
#define WCH 24
#define DL 4
#define TSTEPS 8
#define NPAIR 12
#define PTS (XN*YHN)       // 8320
#define QN (BN*WCH)        // 192

// Conventions: spatial y stored BIT-REVERSED (7-bit) in d_h.
// kx held bit-reversed ("kxs") inside k_mid; d_W is pre-permuted so that
// d_W[d][ky][i*24+o][kxs] = spec_w[d][i][o][brev7(kxs)][ky].

__device__ float  d_h [BN*WCH*XN*YN];                  // [b][c][x][yb]
__device__ __align__(16) float4 d_Hy[BN*YHN*NPAIR*XN]; // [b][ky][pair][x]
__device__ __align__(16) float4 d_Gy[BN*NPAIR*XN*YHN]; // [b][pair][x][ky]
__device__ __align__(16) float2 d_W [DL*YHN*576*XN];   // [d][ky][io][kxs] 153MB

__device__ __forceinline__ float2 cmul(float2 a, float2 b){
    return make_float2(fmaf(a.x,b.x,-a.y*b.y), fmaf(a.x,b.y, a.y*b.x));
}
__device__ __forceinline__ float2 cadd(float2 a, float2 b){ return make_float2(a.x+b.x, a.y+b.y); }
__device__ __forceinline__ float2 csub(float2 a, float2 b){ return make_float2(a.x-b.x, a.y-b.y); }

struct Tw { float2 w1, w1b, w2, w4, w8, w16, w32; };

template<bool INV>
__device__ __forceinline__ float2 tsel(float2 w){ return INV ? make_float2(w.x, -w.y) : w; }

__device__ __forceinline__ Tw make_tw(int l){
    Tw t; float s, c;
    const float P = -6.2831853071795864769f;
    sincosf(P*(float)l/128.f, &s, &c);       t.w1  = make_float2(c, s);
    t.w1b = make_float2(t.w1.y, -t.w1.x);
    t.w2  = cmul(t.w1, t.w1);
    sincosf(P*(float)(l&15)/32.f, &s, &c);   t.w4  = make_float2(c, s);
    sincosf(P*(float)(l&7)/16.f,  &s, &c);   t.w8  = make_float2(c, s);
    sincosf(P*(float)(l&3)/8.f,   &s, &c);   t.w16 = make_float2(c, s);
    t.w32 = (l&1) ? make_float2(0.f, -1.f) : make_float2(1.f, 0.f);
    return t;
}

__device__ __forceinline__ void dif_x4(float2 v[4], int m, float2 w, int l){
    #pragma unroll
    for (int r = 0; r < 4; r++){
        float2 p;
        p.x = __shfl_xor_sync(0xffffffffu, v[r].x, m);
        p.y = __shfl_xor_sync(0xffffffffu, v[r].y, m);
        v[r] = (l & m) ? cmul(csub(p, v[r]), w) : cadd(v[r], p);
    }
}
__device__ __forceinline__ void dit_x4(float2 v[4], int m, float2 w, int l){
    #pragma unroll
    for (int r = 0; r < 4; r++){
        float2 b = (l & m) ? cmul(v[r], w) : v[r];
        float2 p;
        p.x = __shfl_xor_sync(0xffffffffu, b.x, m);
        p.y = __shfl_xor_sync(0xffffffffu, b.y, m);
        v[r] = (l & m) ? csub(p, b) : cadd(b, p);
    }
}

template<bool INV>
__device__ __forceinline__ void fft_dif(float2 v[4], const Tw& t, int l){
    const float2 one = make_float2(1.f, 0.f);
    float2 w1 = tsel<INV>(t.w1), w1b = tsel<INV>(t.w1b), w2 = tsel<INV>(t.w2);
    float2 tm;
    tm = csub(v[0], v[2]); v[0] = cadd(v[0], v[2]); v[2] = cmul(tm, w1);
    tm = csub(v[1], v[3]); v[1] = cadd(v[1], v[3]); v[3] = cmul(tm, w1b);
    tm = csub(v[0], v[1]); v[0] = cadd(v[0], v[1]); v[1] = cmul(tm, w2);
    tm = csub(v[2], v[3]); v[2] = cadd(v[2], v[3]); v[3] = cmul(tm, w2);
    dif_x4(v, 16, tsel<INV>(t.w4),  l);
    dif_x4(v,  8, tsel<INV>(t.w8),  l);
    dif_x4(v,  4, tsel<INV>(t.w16), l);
    dif_x4(v,  2, tsel<INV>(t.w32), l);
    dif_x4(v,  1, one, l);
}

template<bool INV>
__device__ __forceinline__ void fft_dit(float2 v[4], const Tw& t, int l){
    const float2 one = make_float2(1.f, 0.f);
    dit_x4(v,  1, one, l);
    dit_x4(v,  2, tsel<INV>(t.w32), l);
    dit_x4(v,  4, tsel<INV>(t.w16), l);
    dit_x4(v,  8, tsel<INV>(t.w8),  l);
    dit_x4(v, 16, tsel<INV>(t.w4),  l);
    float2 w1 = tsel<INV>(t.w1), w1b = tsel<INV>(t.w1b), w2 = tsel<INV>(t.w2);
    float2 b;
    b = cmul(v[1], w2);  v[1] = csub(v[0], b); v[0] = cadd(v[0], b);
    b = cmul(v[3], w2);  v[3] = csub(v[2], b); v[2] = cadd(v[2], b);
    b = cmul(v[2], w1);  v[2] = csub(v[0], b); v[0] = cadd(v[0], b);
    b = cmul(v[3], w1b); v[3] = csub(v[1], b); v[1] = cadd(v[1], b);
}

__device__ __forceinline__ int brev7(int i){ return (int)(__brev((unsigned)i) >> 25); }

// ---- one-time weight permute: d_W[d][ky][io][kxs] = specw[d][io][brev7(kxs)][ky]
__global__ __launch_bounds__(256) void k_perm(const float2* __restrict__ specw){
    __shared__ float2 sm[YHN][33];
    int bid = blockIdx.x;                  // ((d*576 + io)*4 + r)
    int r   = bid & 3;
    int dio = bid >> 2;
    int w = threadIdx.x >> 5, l = threadIdx.x & 31;
    const float2* src = specw + (size_t)dio*PTS;
    #pragma unroll
    for (int jj = 0; jj < 4; jj++){
        int j  = w + 8*jj;                 // kxs offset 0..31
        int kx = brev7(r*32 + j);
        for (int ky = l; ky < YHN; ky += 32)
            sm[ky][j] = src[kx*65 + ky];
    }
    __syncthreads();
    int d = dio / 576, io = dio - d*576;
    for (int ky = w; ky < YHN; ky += 8)
        d_W[(((size_t)(d*YHN + ky))*576 + io)*XN + r*32 + l] = sm[ky][l];
}

// Forward packed Y-FFT of one channel pair from smem row hn[yb*25 + c], write d_Hy.
__device__ __forceinline__ void ffty_pair(const float* hn, int b, int x, int pr,
                                          const Tw& tw, int l){
    float2 v[4];
    #pragma unroll
    for (int r = 0; r < 4; r++){
        int p = r*32 + l;
        v[r] = make_float2(hn[p*25 + 2*pr], hn[p*25 + 2*pr + 1]);
    }
    fft_dit<false>(v, tw, l);                     // natural ky = r*32+l
    int srcl = (32 - l) & 31;
    float2 s3, s2;
    s3.x = __shfl_sync(0xffffffffu, v[3].x, srcl);
    s3.y = __shfl_sync(0xffffffffu, v[3].y, srcl);
    s2.x = __shfl_sync(0xffffffffu, v[2].x, srcl);
    s2.y = __shfl_sync(0xffffffffu, v[2].y, srcl);
    float2 zm0 = (l == 0) ? v[0] : s3;            // partner of ky=l
    float2 zm1 = (l == 0) ? s3   : s2;            // partner of ky=32+l
    float4* hy = d_Hy + ((size_t)b*YHN*NPAIR + pr)*XN + x;
    float2 zk;
    zk = v[0];                                    // ky = l
    hy[(size_t)l*NPAIR*XN] = make_float4(
        0.5f*(zk.x+zm0.x), 0.5f*(zk.y-zm0.y),
        0.5f*(zk.y+zm0.y), 0.5f*(zm0.x-zk.x));
    zk = v[1];                                    // ky = 32+l
    hy[(size_t)(32+l)*NPAIR*XN] = make_float4(
        0.5f*(zk.x+zm1.x), 0.5f*(zk.y-zm1.y),
        0.5f*(zk.y+zm1.y), 0.5f*(zm1.x-zk.x));
    if (l == 0){                                  // ky = 64
        zk = v[2];
        hy[(size_t)64*NPAIR*XN] = make_float4(zk.x, 0.f, zk.y, 0.f);
    }
}

// ---------------- k_first: h0 = x@in_w+in_b (bitrev-y) + forward Y-FFT ------
__global__ __launch_bounds__(384) void k_first(const float* __restrict__ xin,
                                               const float* __restrict__ inw,
                                               const float* __restrict__ inb){
    __shared__ float2 xv[XN];
    __shared__ float  hn[YN*25];
    int tid = threadIdx.x, wl = tid >> 5, l = tid & 31;
    int bx = blockIdx.x, b = bx >> 7, x = bx & 127;
    if (tid < XN)
        xv[tid] = *(const float2*)(xin + (((size_t)(b*XN + x))*YN + tid)*2);
    __syncthreads();
    for (int idx = tid; idx < WCH*YN; idx += 384){
        int c = idx >> 7, yb = idx & 127;
        float2 v = xv[brev7(yb)];
        float val = inb[c] + v.x*inw[c] + v.y*inw[WCH + c];
        hn[yb*25 + c] = val;
        d_h[((size_t)(b*WCH + c)*XN + x)*YN + yb] = val;
    }
    __syncthreads();
    Tw tw = make_tw(l);
    ffty_pair(hn, b, x, wl, tw, l);
}

// ---- k_mid: X-FFT + spectral mix + inverse X-FFT, block = (b,ky) ----------
__global__ __launch_bounds__(384) void k_mid(int d){
    __shared__ float2 Hs[WCH][XN];    // 24KB
    int tid = threadIdx.x, w = tid >> 5, l = tid & 31;
    int ky = blockIdx.x >> 3, b = blockIdx.x & 7;
    Tw tw = make_tw(l);
    // 1. forward X-FFT (warp = pair), DIF natural->bitrev kxs, into smem
    {
        int pr = w;
        const float4* src = d_Hy + (((size_t)b*YHN + ky)*NPAIR + pr)*XN;
        float2 v[4], u[4];
        #pragma unroll
        for (int r = 0; r < 4; r++){
            float4 f = src[r*32 + l];
            v[r] = make_float2(f.x, f.y);
            u[r] = make_float2(f.z, f.w);
        }
        fft_dif<false>(v, tw, l);
        fft_dif<false>(u, tw, l);
        #pragma unroll
        for (int r = 0; r < 4; r++){
            int kxs = r*32 + l;
            Hs[2*pr    ][kxs] = v[r];
            Hs[2*pr + 1][kxs] = u[r];
        }
    }
    __syncthreads();
    // 2. spectral mix, quarter-wise in place. warp w -> outputs (2w, 2w+1).
    const float2* wbase = d_W + ((size_t)(d*YHN + ky))*576*XN;
    int o0 = 2*w, o1 = o0 + 1;
    #pragma unroll
    for (int r = 0; r < 4; r++){
        int kxs = r*32 + l;
        float2 A  = make_float2(0.f, 0.f);
        float2 Bc = make_float2(0.f, 0.f);
        const float2* wp0 = wbase + (size_t)o0*XN + kxs;
        const float2* wp1 = wbase + (size_t)o1*XN + kxs;
        float2 a0 = wp0[0];
        float2 b0 = wp1[0];
        float2 a1 = wp0[(size_t)WCH*XN];
        float2 b1 = wp1[(size_t)WCH*XN];
        for (int i = 0; i < WCH; i++){
            int ip = (i + 2 < WCH) ? i + 2 : WCH - 1;
            float2 a2 = wp0[(size_t)ip*WCH*XN];
            float2 b2 = wp1[(size_t)ip*WCH*XN];
            float2 hv = Hs[i][kxs];
            A.x  = fmaf( hv.x, a0.x, A.x);
            A.x  = fmaf(-hv.y, a0.y, A.x);
            A.y  = fmaf( hv.x, a0.y, A.y);
            A.y  = fmaf( hv.y, a0.x, A.y);
            Bc.x = fmaf( hv.x, b0.x, Bc.x);
            Bc.x = fmaf(-hv.y, b0.y, Bc.x);
            Bc.y = fmaf( hv.x, b0.y, Bc.y);
            Bc.y = fmaf( hv.y, b0.x, Bc.y);
            a0 = a1; b0 = b1; a1 = a2; b1 = b2;
        }
        __syncthreads();              // all reads of quarter r complete
        Hs[o0][kxs] = A;
        Hs[o1][kxs] = Bc;
    }
    __syncthreads();
    // 3. inverse X-FFT (warp = pair), DIT bitrev->natural x, write d_Gy
    {
        int pr = w;
        float2 v[4], u[4];
        #pragma unroll
        for (int r = 0; r < 4; r++){
            int kxs = r*32 + l;
            v[r] = Hs[2*pr    ][kxs];
            u[r] = Hs[2*pr + 1][kxs];
        }
        fft_dit<true>(v, tw, l);
        fft_dit<true>(u, tw, l);
        float4* dst = d_Gy + (((size_t)b*NPAIR + pr)*XN)*YHN + ky;
        #pragma unroll
        for (int r = 0; r < 4; r++){
            int x = r*32 + l;
            dst[(size_t)x*YHN] = make_float4(v[r].x, v[r].y, u[r].x, u[r].y);
        }
    }
}

// ---- k_tail: inverse Y-rFFT + conv + h update + out proj + next Y-FFT -----
__global__ __launch_bounds__(384) void k_tail(const float* __restrict__ convw,
                                              const float* __restrict__ convb,
                                              const float* __restrict__ outw,
                                              const float* __restrict__ outb,
                                              float* __restrict__ out,
                                              int d, int t, int last, int do_fft){
    __shared__ float hrow [WCH*YN];   // [c][yb]
    __shared__ float x1row[YN*25];    // [yb][c]
    __shared__ float hn   [YN*25];    // [yb][c]
    __shared__ float cw[WCH*WCH];
    __shared__ float cb[WCH];
    __shared__ float ow[WCH];
    __shared__ float ob;
    int tid = threadIdx.x, wl = tid >> 5, l = tid & 31;
    int bx = blockIdx.x, b = bx >> 7, x = bx & 127;
    Tw tw = make_tw(l);
    float* hpb = d_h + (size_t)b*WCH*XN*YN + (size_t)x*YN;
    for (int idx = tid; idx < WCH*YN; idx += 384){
        int c = idx >> 7, y = idx & 127;
        hrow[idx] = hpb[(size_t)c*XN*YN + y];
    }
    for (int idx = tid; idx < WCH*WCH; idx += 384) cw[idx] = convw[d*WCH*WCH + idx];
    if (tid < WCH){ cb[tid] = convb[d*WCH + tid]; ow[tid] = outw[tid]; }
    if (tid == 0) ob = outb[0];
    // inverse Y (packed pair): warp wl = pair; coalesced d_Gy rows
    {
        int pr = wl;
        const float4* gy = d_Gy + (((size_t)b*NPAIR + pr)*XN + x)*YHN;
        float2 z[4];
        {   // k = l (DC imag discarded at l==0)
            float4 f = gy[l];
            float2 g0 = make_float2(f.x, f.y), g1 = make_float2(f.z, f.w);
            if (l == 0){ g0.y = 0.f; g1.y = 0.f; }
            z[0] = make_float2(g0.x - g1.y, g0.y + g1.x);
        }
        {   // k = 32+l
            float4 f = gy[32 + l];
            z[1] = make_float2(f.x - f.w, f.y + f.z);
        }
        {   // k = 64+l: l==0 direct (Nyquist); else mirror km=64-l
            int km = 64 - l;
            float4 f = gy[km];
            float2 g0 = make_float2(f.x, f.y), g1 = make_float2(f.z, f.w);
            if (l == 0){
                g0.y = 0.f; g1.y = 0.f;
                z[2] = make_float2(g0.x - g1.y, g0.y + g1.x);
            } else {
                z[2] = make_float2(g0.x + g1.y, g1.x - g0.y);
            }
        }
        {   // k = 96+l: mirror km = 32-l
            int km = 32 - l;
            float4 f = gy[km];
            z[3] = make_float2(f.x + f.w, f.z - f.y);
        }
        fft_dif<true>(z, tw, l);
        const float sc = 1.f/16384.f;
        #pragma unroll
        for (int r = 0; r < 4; r++){
            int p = r*32 + l;
            x1row[p*25 + 2*pr    ] = z[r].x * sc;
            x1row[p*25 + 2*pr + 1] = z[r].y * sc;
        }
    }
    __syncthreads();
    // conv + relu-combine: thread -> (y, o-group of 8)
    {
        int y = tid & 127, og = tid >> 7, o0 = og*8;
        float acc[8];
        #pragma unroll
        for (int j = 0; j < 8; j++) acc[j] = cb[o0 + j];
        #pragma unroll
        for (int i = 0; i < WCH; i++){
            float hv = hrow[i*YN + y];
            #pragma unroll
            for (int j = 0; j < 8; j++) acc[j] = fmaf(hv, cw[i*WCH + o0 + j], acc[j]);
        }
        #pragma unroll
        for (int j = 0; j < 8; j++){
            float v = x1row[y*25 + o0 + j];
            hn[y*25 + o0 + j] = fmaxf(v, 0.f) + acc[j];
        }
    }
    __syncthreads();
    for (int idx = tid; idx < WCH*YN; idx += 384){
        int c = idx >> 7, yy = idx & 127;
        hpb[(size_t)c*XN*YN + yy] = hn[yy*25 + c];
    }
    if (last){
        for (int yy = tid; yy < YN; yy += 384){
            float a = ob;
            #pragma unroll
            for (int c = 0; c < WCH; c++) a = fmaf(hn[yy*25 + c], ow[c], a);
            out[(((size_t)b*TSTEPS + t)*XN + x)*YN + brev7(yy)] = a;
        }
    }
    if (do_fft)
        ffty_pair(hn, b, x, wl, tw, l);
}

// ---------------------------------------------------------------------------
extern "C" void kernel_launch(void* const* d_in, const int* in_sizes, int n_in,
                              void* d_out, int out_size){
    (void)in_sizes; (void)n_in; (void)out_size;
    const float* x     = (const float*)d_in[0];
    const float* in_w  = (const float*)d_in[1];
    const float* in_b  = (const float*)d_in[2];
    const float2* specw= (const float2*)d_in[3];
    const float* convw = (const float*)d_in[4];
    const float* convb = (const float*)d_in[5];
    const float* outw  = (const float*)d_in[6];
    const float* outb  = (const float*)d_in[7];
    float* out = (float*)d_out;

    k_perm <<<DL*576*4, 256>>>(specw);
    k_first<<<BN*XN, 384>>>(x, in_w, in_b);
    for (int t = 0; t < TSTEPS; t++){
        for (int d = 0; d < DL; d++){
            k_mid <<<BN*YHN, 384>>>(d);
            int last   = (d == DL-1);
            int do_fft = !(t == TSTEPS-1 && d == DL-1);
            k_tail<<<BN*XN, 384>>>(convw, convb, outw, outb, out, d, t, last, do_fft);
        }
    }
}